// round 1
// baseline (speedup 1.0000x reference)
#include <cuda_runtime.h>
#include <math.h>

#define FULLMASK 0xffffffffu

// ---------------------------------------------------------------------------
// 10-qubit statevector per warp: amplitude index i = r*32 + lane (r = register
// index 0..31, lane = 0..31). Wire w <-> bit w of i. Wires 0..4 live across
// lanes (shfl), wires 5..9 live across registers (pure reg math).
// ---------------------------------------------------------------------------

__device__ __forceinline__ void ry_lane(float st[32], int w, float c, float s, int lane) {
    // new0 = c*a0 - s*a1 ; new1 = s*a0 + c*a1  (a1 = partner with bit w set)
    float sp = ((lane >> w) & 1) ? s : -s;
    int m = 1 << w;
#pragma unroll
    for (int r = 0; r < 32; r++) {
        float o = __shfl_xor_sync(FULLMASK, st[r], m);
        st[r] = fmaf(sp, o, c * st[r]);
    }
}

__device__ __forceinline__ void ry_reg(float st[32], int b, float c, float s) {
    int m = 1 << b;
#pragma unroll
    for (int r = 0; r < 32; r++) {
        if ((r & m) == 0) {
            float a0 = st[r], a1 = st[r + m];
            st[r]     = fmaf(-s, a1, c * a0);
            st[r + m] = fmaf( s, a0, c * a1);
        }
    }
}

// CNOT: ctrl and tgt both lane bits
__device__ __forceinline__ void cnot_ll(float st[32], int cb, int tb, int lane) {
    bool hi = (lane >> cb) & 1;
    int m = 1 << tb;
#pragma unroll
    for (int r = 0; r < 32; r++) {
        float o = __shfl_xor_sync(FULLMASK, st[r], m);
        st[r] = hi ? o : st[r];
    }
}

// CNOT: ctrl and tgt both register bits
__device__ __forceinline__ void cnot_rr(float st[32], int cb, int tb) {
    int mc = 1 << cb, mt = 1 << tb;
#pragma unroll
    for (int r = 0; r < 32; r++) {
        if ((r & mc) && !(r & mt)) {
            float t = st[r];
            st[r] = st[r + mt];
            st[r + mt] = t;
        }
    }
}

__global__ __launch_bounds__(256)
void dq_kernel(const float* __restrict__ x,
               const float* __restrict__ W1,
               const float* __restrict__ b1,
               const float* __restrict__ qw,
               const float* __restrict__ W2,
               const float* __restrict__ b2,
               float* __restrict__ out)
{
    __shared__ float sW1[10][512];   // W1 transposed: [q][d]
    __shared__ float sW2[640];       // [10][64]
    __shared__ float sb2[64];
    __shared__ float sb1[10];
    __shared__ float sqc[6][10];
    __shared__ float sqs[6][10];

    const int tid = threadIdx.x;

    // Stage weights
#pragma unroll 4
    for (int i = tid; i < 5120; i += 256) {
        int d = i / 10, q = i - d * 10;
        sW1[q][d] = W1[i];
    }
    for (int i = tid; i < 640; i += 256) sW2[i] = W2[i];
    if (tid < 64) sb2[tid] = b2[tid];
    if (tid < 10) sb1[tid] = b1[tid];
    if (tid < 60) {
        float s, c;
        sincosf(0.5f * qw[tid], &s, &c);
        sqc[tid / 10][tid % 10] = c;
        sqs[tid / 10][tid % 10] = s;
    }
    __syncthreads();

    const int warp = tid >> 5;
    const int lane = tid & 31;
    const int sample = blockIdx.x * 8 + warp;
    const float* xr = x + (size_t)sample * 512;

    // ---- angles = tanh(x@W1 + b1) * pi/2; per-wire u/v for product state ----
    float xv[16];
#pragma unroll
    for (int j = 0; j < 16; j++) xv[j] = xr[lane + 32 * j];

    float u[10], v[10];
#pragma unroll
    for (int q = 0; q < 10; q++) {
        float p = 0.f;
#pragma unroll
        for (int j = 0; j < 16; j++) p = fmaf(xv[j], sW1[q][lane + 32 * j], p);
#pragma unroll
        for (int off = 16; off; off >>= 1) p += __shfl_xor_sync(FULLMASK, p, off);
        float ang = tanhf(p + sb1[q]) * 1.57079632679489662f;
        float s, c;
        sincosf(0.5f * ang, &s, &c);
        // RY(theta) applied to |+> : (c-s)/sqrt2, (c+s)/sqrt2
        u[q] = (c - s) * 0.70710678118654752f;
        v[q] = (c + s) * 0.70710678118654752f;
    }

    // ---- build product state: st[r] = prod over bits ----
    float st[32];
    float L = 1.f;
#pragma unroll
    for (int w = 0; w < 5; w++) L *= ((lane >> w) & 1) ? v[w] : u[w];
    st[0] = L;
#pragma unroll
    for (int b = 0; b < 5; b++) {
        const int m = 1 << b;
        const int w = 5 + b;
#pragma unroll
        for (int r = 0; r < 32; r++) {
            if (r < m) {
                st[r + m] = st[r] * v[w];
                st[r]     = st[r] * u[w];
            }
        }
    }

    // ---- 6 layers: brick-wall CNOTs + trainable RY ----
#pragma unroll
    for (int k = 0; k < 6; k++) {
        // even CNOTs: (0,1) (2,3) (4,5) (6,7) (8,9)
        cnot_ll(st, 0, 1, lane);
        cnot_ll(st, 2, 3, lane);
        // (4,5): ctrl = lane bit 4, tgt = reg bit 0
        if (lane & 16) {
#pragma unroll
            for (int r = 0; r < 32; r += 2) {
                float t = st[r]; st[r] = st[r + 1]; st[r + 1] = t;
            }
        }
        cnot_rr(st, 1, 2);  // wires (6,7)
        cnot_rr(st, 3, 4);  // wires (8,9)
        // odd CNOTs: (1,2) (3,4) (5,6) (7,8)
        cnot_ll(st, 1, 2, lane);
        cnot_ll(st, 3, 4, lane);
        cnot_rr(st, 0, 1);  // wires (5,6)
        cnot_rr(st, 2, 3);  // wires (7,8)
        // RY layer
#pragma unroll
        for (int w = 0; w < 5; w++) ry_lane(st, w, sqc[k][w], sqs[k][w], lane);
#pragma unroll
        for (int w = 5; w < 10; w++) ry_reg(st, w - 5, sqc[k][w], sqs[k][w]);
    }

    // ---- measurement: <Z_w> = sum_i sign_w(i) * |psi_i|^2 ----
    float T = 0.f;
#pragma unroll
    for (int r = 0; r < 32; r++) {
        st[r] = st[r] * st[r];
        T += st[r];
    }

    float e[10];
#pragma unroll
    for (int w = 0; w < 5; w++) {
        float val = ((lane >> w) & 1) ? -T : T;
#pragma unroll
        for (int off = 16; off; off >>= 1) val += __shfl_xor_sync(FULLMASK, val, off);
        e[w] = val;
    }
#pragma unroll
    for (int b = 0; b < 5; b++) {
        float acc = 0.f;
#pragma unroll
        for (int r = 0; r < 32; r++) acc += ((r >> b) & 1) ? -st[r] : st[r];
#pragma unroll
        for (int off = 16; off; off >>= 1) acc += __shfl_xor_sync(FULLMASK, acc, off);
        e[5 + b] = acc;
    }

    // ---- out = e @ W2 + b2 ----
#pragma unroll
    for (int t = 0; t < 2; t++) {
        int o = lane + 32 * t;
        float acc = sb2[o];
#pragma unroll
        for (int q = 0; q < 10; q++) acc = fmaf(e[q], sW2[q * 64 + o], acc);
        out[(size_t)sample * 64 + o] = acc;
    }
}

extern "C" void kernel_launch(void* const* d_in, const int* in_sizes, int n_in,
                              void* d_out, int out_size) {
    const float* x  = (const float*)d_in[0];
    const float* W1 = (const float*)d_in[1];
    const float* b1 = (const float*)d_in[2];
    const float* qw = (const float*)d_in[3];
    const float* W2 = (const float*)d_in[4];
    const float* b2 = (const float*)d_in[5];
    float* out = (float*)d_out;

    int B = in_sizes[0] / 512;          // 8192
    int grid = B / 8;                   // 8 samples (warps) per 256-thread block
    dq_kernel<<<grid, 256>>>(x, W1, b1, qw, W2, b2, out);
}

// round 2
// speedup vs baseline: 1.4631x; 1.4631x over previous
#include <cuda_runtime.h>
#include <math.h>

#define FULLMASK 0xffffffffu

// Composed register-bit CNOT permutation source index (wires 5..9 = reg bits 0..4):
// src bits = (r0, r1^r0, r2^r1^r0, r3^r2, r4^r3^r2)
#define RSRC(r) ( ((r)&1) \
    | (((((r)>>1)^(r))&1)<<1) \
    | (((((r)>>2)^((r)>>1)^(r))&1)<<2) \
    | (((((r)>>3)^((r)>>2))&1)<<3) \
    | (((((r)>>4)^((r)>>3)^((r)>>2))&1)<<4) )

__device__ __forceinline__ float fast_tanh(float x) {
    // tanh(x) = (e-1)/(e+1), e = 2^(2x*log2e). MUFU.EX2 + MUFU.RCP: ~1e-7 rel err.
    float e;
    asm("ex2.approx.f32 %0, %1;" : "=f"(e) : "f"(x * 2.88539008177792681f));
    return (e - 1.0f) * __frcp_rn(e + 1.0f);
}

__global__ __launch_bounds__(256)
void dq_kernel(const float* __restrict__ x,
               const float* __restrict__ W1,
               const float* __restrict__ b1,
               const float* __restrict__ qw,
               const float* __restrict__ W2,
               const float* __restrict__ b2,
               float* __restrict__ out)
{
    __shared__ alignas(16) float sW1[10][512];   // W1 transposed: [q][d]
    __shared__ float sW2[640];       // [10][64]
    __shared__ float sb2[64];
    __shared__ float sb1[10];
    __shared__ float sqt[6][10];     // tan(theta/2)
    __shared__ float sC[6];          // prod of 10 cos(theta/2) per layer
    __shared__ float scc[64];        // temp cosines

    const int tid = threadIdx.x;

    // ---- stage weights ----
#pragma unroll 4
    for (int i = tid; i < 5120; i += 256) {
        int d = i / 10, q = i - d * 10;
        sW1[q][d] = W1[i];
    }
    for (int i = tid; i < 640; i += 256) sW2[i] = W2[i];
    if (tid < 64) sb2[tid] = b2[tid];
    if (tid < 10) sb1[tid] = b1[tid];
    if (tid < 60) {
        float th = 0.5f * qw[tid];
        float s = __sinf(th), c = __cosf(th);
        sqt[tid / 10][tid % 10] = s * __frcp_rn(c);
        scc[tid] = c;
    }
    __syncthreads();
    if (tid < 6) {
        float p = 1.f;
#pragma unroll
        for (int w = 0; w < 10; w++) p *= scc[tid * 10 + w];
        sC[tid] = p;
    }
    __syncthreads();

    const int warp = tid >> 5;
    const int lane = tid & 31;
    const int sample = blockIdx.x * 8 + warp;
    const float* xr = x + (size_t)sample * 512;

    // Composed lane-CNOT permutation source lane:
    // src bits = (b0, b1^b0, b2^b1, b3^b2^b1, b4^b3)
    const int lsrc = (lane & 1)
        | ((((lane >> 1) ^ lane) & 1) << 1)
        | ((((lane >> 2) ^ (lane >> 1)) & 1) << 2)
        | ((((lane >> 3) ^ (lane >> 2) ^ (lane >> 1)) & 1) << 3)
        | ((((lane >> 4) ^ (lane >> 3)) & 1) << 4);
    // CNOT(4,5) condition after conjugation through the lane perm: b4^b3
    const bool qsw = (((lane >> 4) ^ (lane >> 3)) & 1);
    float sgn[5];
#pragma unroll
    for (int w = 0; w < 5; w++) sgn[w] = ((lane >> w) & 1) ? 1.f : -1.f;

    // ---- angles = tanh(x@W1 + b1) * pi/2; per-wire u/v for product state ----
    const float4* x4 = (const float4*)xr;
    float4 xv[4];
#pragma unroll
    for (int t = 0; t < 4; t++) xv[t] = x4[lane + 32 * t];

    float u[10], v[10];
#pragma unroll
    for (int q = 0; q < 10; q++) {
        const float4* w4 = (const float4*)(&sW1[q][0]);
        float p = 0.f;
#pragma unroll
        for (int t = 0; t < 4; t++) {
            float4 wv = w4[lane + 32 * t];
            p = fmaf(xv[t].x, wv.x, p);
            p = fmaf(xv[t].y, wv.y, p);
            p = fmaf(xv[t].z, wv.z, p);
            p = fmaf(xv[t].w, wv.w, p);
        }
#pragma unroll
        for (int off = 16; off; off >>= 1) p += __shfl_xor_sync(FULLMASK, p, off);
        float ang = fast_tanh(p + sb1[q]) * 1.57079632679489662f;
        float hh = 0.5f * ang;
        float s = __sinf(hh), c = __cosf(hh);
        u[q] = (c - s) * 0.70710678118654752f;
        v[q] = (c + s) * 0.70710678118654752f;
    }

    // ---- build product state ----
    float st[32];
    float L = 1.f;
#pragma unroll
    for (int w = 0; w < 5; w++) L *= ((lane >> w) & 1) ? v[w] : u[w];
    st[0] = L;
#pragma unroll
    for (int b = 0; b < 5; b++) {
        const int m = 1 << b;
        const int w = 5 + b;
#pragma unroll
        for (int r = 0; r < 32; r++) {
            if (r < m) {
                st[r + m] = st[r] * v[w];
                st[r]     = st[r] * u[w];
            }
        }
    }

    // ---- 6 layers ----
#pragma unroll
    for (int k = 0; k < 6; k++) {
        // (1) all 4 lane-CNOTs as ONE composed shuffle
#pragma unroll
        for (int r = 0; r < 32; r++)
            st[r] = __shfl_sync(FULLMASK, st[r], lsrc);
        // (2) CNOT(4,5): conditional swap of reg-bit0 pairs
#pragma unroll
        for (int i = 0; i < 16; i++) {
            float a = st[2 * i], b = st[2 * i + 1];
            st[2 * i]     = qsw ? b : a;
            st[2 * i + 1] = qsw ? a : b;
        }
        // (3) all 4 reg-CNOTs: pure compile-time register relabeling (free)
        {
            float tp[32];
#pragma unroll
            for (int r = 0; r < 32; r++) tp[r] = st[RSRC(r)];
#pragma unroll
            for (int r = 0; r < 32; r++) st[r] = tp[r];
        }
        // (4) RY on lane wires, cosine deferred: st = st + (+-tan)*partner
#pragma unroll
        for (int w = 0; w < 5; w++) {
            float tq = sgn[w] * sqt[k][w];
            const int m = 1 << w;
#pragma unroll
            for (int r = 0; r < 32; r++) {
                float o = __shfl_xor_sync(FULLMASK, st[r], m);
                st[r] = fmaf(tq, o, st[r]);
            }
        }
        // (5) RY on reg wires, cosine deferred
#pragma unroll
        for (int b = 0; b < 5; b++) {
            float tw = sqt[k][5 + b];
            const int m = 1 << b;
#pragma unroll
            for (int r = 0; r < 32; r++) {
                if ((r & m) == 0) {
                    float a0 = st[r], a1 = st[r + m];
                    st[r]     = fmaf(-tw, a1, a0);
                    st[r + m] = fmaf( tw, a0, a1);
                }
            }
        }
        // (6) apply the 10 deferred cosines at once
        {
            float Ck = sC[k];
#pragma unroll
            for (int r = 0; r < 32; r++) st[r] *= Ck;
        }
    }

    // ---- measurement ----
    float T = 0.f;
#pragma unroll
    for (int r = 0; r < 32; r++) {
        st[r] = st[r] * st[r];
        T += st[r];
    }

    float e[10];
    // lane wires 0..4: shared Walsh tree over lanes (15 shfl)
    {
        float s = T;
#pragma unroll
        for (int w = 0; w < 5; w++) {
            const int m = 1 << w;
            float o = __shfl_xor_sync(FULLMASK, s, m);
            float d = ((lane >> w) & 1) ? (o - s) : (s - o);
            s = s + o;
#pragma unroll
            for (int mm = 2 * m; mm < 32; mm <<= 1)
                d += __shfl_xor_sync(FULLMASK, d, mm);
            e[w] = d;
        }
    }
    // reg wires 5..9: shared pair-tree over registers, then lane all-reduce
    {
        float p0[16], p1[8], p2[4], p3[2];
        float d0 = 0.f, d1 = 0.f, d2 = 0.f, d3 = 0.f, d4;
#pragma unroll
        for (int i = 0; i < 16; i++) { p0[i] = st[2*i] + st[2*i+1]; d0 += st[2*i] - st[2*i+1]; }
#pragma unroll
        for (int i = 0; i < 8; i++)  { p1[i] = p0[2*i] + p0[2*i+1]; d1 += p0[2*i] - p0[2*i+1]; }
#pragma unroll
        for (int i = 0; i < 4; i++)  { p2[i] = p1[2*i] + p1[2*i+1]; d2 += p1[2*i] - p1[2*i+1]; }
#pragma unroll
        for (int i = 0; i < 2; i++)  { p3[i] = p2[2*i] + p2[2*i+1]; d3 += p2[2*i] - p2[2*i+1]; }
        d4 = p3[0] - p3[1];
        float dd[5] = {d0, d1, d2, d3, d4};
#pragma unroll
        for (int b = 0; b < 5; b++) {
            float acc = dd[b];
#pragma unroll
            for (int off = 16; off; off >>= 1) acc += __shfl_xor_sync(FULLMASK, acc, off);
            e[5 + b] = acc;
        }
    }

    // ---- out = e @ W2 + b2 ----
#pragma unroll
    for (int t = 0; t < 2; t++) {
        int o = lane + 32 * t;
        float acc = sb2[o];
#pragma unroll
        for (int q = 0; q < 10; q++) acc = fmaf(e[q], sW2[q * 64 + o], acc);
        out[(size_t)sample * 64 + o] = acc;
    }
}

extern "C" void kernel_launch(void* const* d_in, const int* in_sizes, int n_in,
                              void* d_out, int out_size) {
    const float* x  = (const float*)d_in[0];
    const float* W1 = (const float*)d_in[1];
    const float* b1 = (const float*)d_in[2];
    const float* qw = (const float*)d_in[3];
    const float* W2 = (const float*)d_in[4];
    const float* b2 = (const float*)d_in[5];
    float* out = (float*)d_out;

    int B = in_sizes[0] / 512;          // 8192
    int grid = B / 8;                   // 8 samples (warps) per 256-thread block
    dq_kernel<<<grid, 256>>>(x, W1, b1, qw, W2, b2, out);
}